// round 11
// baseline (speedup 1.0000x reference)
// R11: R10 tensor-core design (audited: fragment layouts, bank mapping, tail
// guards all verified) + KS==1 fill specialization for the 144-chunk DCN GEMM.
#include <cuda_runtime.h>

#define BSZ 2
#define Hh 96
#define Ww 96
#define HW (Hh*Ww)
#define G 8
#define K 9
#define CG 16
#define CIN_DCN 1152   // 128*9

typedef unsigned int u32;

// ---------------- tf32 helpers ----------------
__device__ __forceinline__ u32 tf32r(float f) {       // round-to-nearest tf32
    u32 u; asm("cvt.rna.tf32.f32 %0, %1;" : "=r"(u) : "f"(f)); return u;
}
__device__ __forceinline__ void mma8(float* d, const u32* a, u32 b0, u32 b1) {
    asm volatile(
        "mma.sync.aligned.m16n8k8.row.col.f32.tf32.tf32.f32 "
        "{%0,%1,%2,%3},{%4,%5,%6,%7},{%8,%9},{%0,%1,%2,%3};"
        : "+f"(d[0]), "+f"(d[1]), "+f"(d[2]), "+f"(d[3])
        : "r"(a[0]), "r"(a[1]), "r"(a[2]), "r"(a[3]), "r"(b0), "r"(b1));
}

// ---------------- scratch (no allocations allowed) ----------------
__device__ float g_t1  [BSZ*128*HW];
__device__ float g_t2  [BSZ*128*HW];
__device__ float g_tom [BSZ*216*HW];
__device__ float g_tv  [BSZ*CIN_DCN*HW];
__device__ float g_tfea[BSZ*128*HW];
// packed hi/lo tf32 weights, fragment order
__device__ float g_pk1 [294912];
__device__ float g_pk2 [294912];
__device__ float g_pkom[589824];
__device__ float g_pkdc[294912];
__device__ float g_pkrq[589824];

// ---------------- weight pack: gmem w[OC][CIN][S] -> fragment-ordered hi/lo ----------------
// tid = ((tile*NCH + chunk)*S + s)*128 + frag*32 + lane; 8 floats per tid:
// [0..3] = a0..a3 hi, [4..7] = a0..a3 lo. mma A frag (16oc x 8c):
//   a_i: oc = tile*64 + (frag>>1)*32 + (frag&1)*16 + (lane>>2) + (i&1)*8
//        c  = chunk*8 + (lane&3) + (i>>1)*4
__global__ void pack_w(const float* __restrict__ wgt, float* __restrict__ dst,
                       int OC, int CIN, int S, int OCT)
{
    int tid = blockIdx.x * blockDim.x + threadIdx.x;
    int NCH = CIN >> 3;
    int total = OCT * NCH * S * 128;
    if (tid >= total) return;
    int lane = tid & 31;
    int frag = (tid >> 5) & 3;
    int rest = tid >> 7;
    int s = rest % S; rest /= S;
    int chunk = rest % NCH;
    int tile  = rest / NCH;
    float hi[4], lo[4];
#pragma unroll
    for (int i = 0; i < 4; i++) {
        int oc = tile*64 + (frag>>1)*32 + (frag&1)*16 + (lane>>2) + (i&1)*8;
        int c  = chunk*8 + (lane&3) + (i>>1)*4;
        float w = (oc < OC) ? wgt[((size_t)oc*CIN + c)*S + s] : 0.f;
        u32 h = tf32r(w);
        float hf = __uint_as_float(h);
        hi[i] = hf;
        lo[i] = __uint_as_float(tf32r(w - hf));
    }
    float4* d4 = (float4*)(dst + (size_t)tid*8);
    d4[0] = make_float4(hi[0], hi[1], hi[2], hi[3]);
    d4[1] = make_float4(lo[0], lo[1], lo[2], lo[3]);
}

// ---------------- conv-as-GEMM via mma.sync tf32 (hi/lo split) ----------------
// Block: 256 thr = 8 warps (2 M x 4 N). Block tile: 64 oc x (32w x 4h) px.
// Warp: 32 oc x 32 px (one pixel row). K-loop: CIN/8 chunks x KS*KS shifts.
// s_in: fp32 split into hi/lo tf32, [c8][y6][x36] (pad 36 => B conflict-free).
template<int CIN, int OC, int KS, int MODE, bool RELU>
__global__ void __launch_bounds__(256) convmma_k(
    const float* __restrict__ x, const float* __restrict__ x2,
    const float* __restrict__ wpk, const float* __restrict__ bias,
    float* __restrict__ out)
{
    constexpr int S    = KS*KS;
    constexpr int PADH = KS >> 1;
    constexpr int NCH  = CIN >> 3;
    constexpr int OCT  = (OC + 63) >> 6;
    constexpr bool FULL = (OC & 63) == 0;

    __shared__ float s_hi[8][6][36];
    __shared__ float s_lo[8][6][36];

    const int t = threadIdx.x, lane = t & 31, warp = t >> 5;
    const int wm = warp >> 2, wn = warp & 3;
    const int g = lane >> 2, tig = lane & 3;
    const int x0 = blockIdx.x * 32, y0 = blockIdx.y * 4;
    const int b  = blockIdx.z / OCT, ot = blockIdx.z % OCT;

    float d[2][4][4];
#pragma unroll
    for (int f = 0; f < 2; f++)
#pragma unroll
        for (int nf = 0; nf < 4; nf++)
#pragma unroll
            for (int r = 0; r < 4; r++) d[f][nf][r] = 0.f;

    uint4 avh[2][2], avl[2][2];   // A double-buffer: [buf][mfrag] hi/lo
    const float* wblk = wpk + (size_t)ot * NCH * S * 1024 + (wm*2)*256 + lane*8;

    for (int chunk = 0; chunk < NCH; chunk++) {
        __syncthreads();
        if (KS == 1) {
            // 1x1: no halo -> fill only 8c x 4y x 32x
            for (int idx = t; idx < 1024; idx += 256) {
                int xi  = idx & 31;
                int rem = idx >> 5;
                int yy  = rem & 3;
                int c   = rem >> 2;
                size_t off = ((size_t)b*CIN + chunk*8 + c)*HW
                           + (size_t)(y0 + yy)*Ww + (x0 + xi);
                float v = x[off];
                u32 h = tf32r(v);
                float hf = __uint_as_float(h);
                s_hi[c][yy][xi] = hf;
                s_lo[c][yy][xi] = __uint_as_float(tf32r(v - hf));
            }
        } else {
            // 3x3: 8c x 6y x 36x with halo, zero-padded
            for (int idx = t; idx < 1728; idx += 256) {
                int xi  = idx % 36;
                int rem = idx / 36;
                int yy  = rem % 6;
                int c   = rem / 6;
                int gx = x0 + xi - PADH, gy = y0 + yy - PADH;
                int cg = chunk*8 + c;
                float v = 0.f;
                if (gx >= 0 && gx < Ww && gy >= 0 && gy < Hh) {
                    if (MODE == 2) {
                        const float* src = (cg < 128)
                            ? (x  + ((size_t)b*128 + cg      )*HW)
                            : (x2 + ((size_t)b*128 + (cg-128))*HW);
                        v = src[gy*Ww + gx];
                    } else {
                        size_t off = ((size_t)b*CIN + cg)*HW + (size_t)gy*Ww + gx;
                        v = x[off];
                        if (MODE == 1) v -= x2[off];
                    }
                }
                u32 h = tf32r(v);
                float hf = __uint_as_float(h);
                s_hi[c][yy][xi] = hf;
                s_lo[c][yy][xi] = __uint_as_float(tf32r(v - hf));
            }
        }
        __syncthreads();

        // preload A for shift 0
        {
            const float* p = wblk + (size_t)chunk * S * 1024;
            avh[0][0] = *(const uint4*)(p);
            avl[0][0] = *(const uint4*)(p + 4);
            avh[0][1] = *(const uint4*)(p + 256);
            avl[0][1] = *(const uint4*)(p + 260);
        }
        int pb = 0;
#pragma unroll 1
        for (int s = 0; s < S; s++) {
            if (s + 1 < S) {   // prefetch next shift's A
                const float* p = wblk + ((size_t)chunk * S + s + 1) * 1024;
                avh[pb^1][0] = *(const uint4*)(p);
                avl[pb^1][0] = *(const uint4*)(p + 4);
                avh[pb^1][1] = *(const uint4*)(p + 256);
                avl[pb^1][1] = *(const uint4*)(p + 260);
            }
            const int ky = (KS == 3) ? s / 3 : 0;
            const int kx = (KS == 3) ? s % 3 : 0;
            const int by = wn + ky;
#pragma unroll
            for (int nf = 0; nf < 4; nf++) {
                int bx = nf*8 + g + kx;
                u32 b0h = __float_as_uint(s_hi[tig    ][by][bx]);
                u32 b1h = __float_as_uint(s_hi[tig + 4][by][bx]);
                u32 b0l = __float_as_uint(s_lo[tig    ][by][bx]);
                u32 b1l = __float_as_uint(s_lo[tig + 4][by][bx]);
#pragma unroll
                for (int f = 0; f < 2; f++) {
                    const u32* ah = (const u32*)&avh[pb][f];
                    const u32* al = (const u32*)&avl[pb][f];
                    mma8(d[f][nf], ah, b0h, b1h);   // hi*hi
                    mma8(d[f][nf], al, b0h, b1h);   // lo(w)*hi(x)
                    mma8(d[f][nf], ah, b0l, b1l);   // hi(w)*lo(x)
                }
            }
            pb ^= 1;
        }
    }

    // ---- epilogue: D(16x8): c0 (g,2tig) c1 (g,2tig+1) c2 (g+8,..) c3 ----
    const int yy = y0 + wn;
#pragma unroll
    for (int f = 0; f < 2; f++) {
        int ocr0 = ot*64 + wm*32 + f*16 + g;
        int ocr1 = ocr0 + 8;
        float bi0 = (FULL || ocr0 < OC) ? bias[ocr0] : 0.f;
        float bi1 = (FULL || ocr1 < OC) ? bias[ocr1] : 0.f;
#pragma unroll
        for (int nf = 0; nf < 4; nf++) {
            int xx = x0 + nf*8 + 2*tig;
            float v0 = d[f][nf][0] + bi0, v1 = d[f][nf][1] + bi0;
            float v2 = d[f][nf][2] + bi1, v3 = d[f][nf][3] + bi1;
            if (RELU) {
                v0 = fmaxf(v0, 0.f); v1 = fmaxf(v1, 0.f);
                v2 = fmaxf(v2, 0.f); v3 = fmaxf(v3, 0.f);
            }
            if (FULL || ocr0 < OC)
                *(float2*)&out[((size_t)b*OC + ocr0)*HW + (size_t)yy*Ww + xx] = make_float2(v0, v1);
            if (FULL || ocr1 < OC)
                *(float2*)&out[((size_t)b*OC + ocr1)*HW + (size_t)yy*Ww + xx] = make_float2(v2, v3);
        }
    }
}

// ---------------- deformable sampling (unchanged, 61us measured) ----------------
__global__ void dcn_sample_k(const float* __restrict__ x, const float* __restrict__ om,
                             float* __restrict__ v)
{
    int t = blockIdx.x * blockDim.x + threadIdx.x;
    const int total = BSZ * G * K * HW;
    if (t >= total) return;
    int hw = t % HW;
    int k  = (t / HW) % K;
    int g  = (t / (HW * K)) % G;
    int b  =  t / (HW * K * G);
    int h = hw / Ww, w = hw % Ww;

    const float* omb = om + (size_t)b*216*HW;
    float dy = omb[(size_t)(g*18 + 2*k    )*HW + hw];
    float dx = omb[(size_t)(g*18 + 2*k + 1)*HW + hw];
    float mk = omb[(size_t)(144 + g*9 + k )*HW + hw];
    float m  = 1.f / (1.f + __expf(-mk));

    int ky = k / 3, kx = k % 3;
    float py = dy + (float)(ky + h - 1);
    float px = dx + (float)(kx + w - 1);
    float y0f = floorf(py), x0f = floorf(px);
    float ly = py - y0f, lx = px - x0f;
    int y0 = (int)y0f, x0 = (int)x0f;
    int y1 = y0 + 1,   x1 = x0 + 1;
    bool vy0 = (y0 >= 0) & (y0 < Hh), vy1 = (y1 >= 0) & (y1 < Hh);
    bool vx0 = (x0 >= 0) & (x0 < Ww), vx1 = (x1 >= 0) & (x1 < Ww);
    int yc0 = min(max(y0, 0), Hh-1), yc1 = min(max(y1, 0), Hh-1);
    int xc0 = min(max(x0, 0), Ww-1), xc1 = min(max(x1, 0), Ww-1);

    float w00 = (vy0 & vx0) ? (1.f-ly)*(1.f-lx)*m : 0.f;
    float w01 = (vy0 & vx1) ? (1.f-ly)*lx      *m : 0.f;
    float w10 = (vy1 & vx0) ? ly*(1.f-lx)      *m : 0.f;
    float w11 = (vy1 & vx1) ? ly*lx            *m : 0.f;

    int i00 = yc0*Ww + xc0, i01 = yc0*Ww + xc1;
    int i10 = yc1*Ww + xc0, i11 = yc1*Ww + xc1;

    const float* xb = x + ((size_t)b*128 + g*CG)*HW;
    float* vb = v + (size_t)b*CIN_DCN*HW + (size_t)(g*CG)*9*HW + (size_t)k*HW + hw;

#pragma unroll
    for (int c = 0; c < CG; c++) {
        const float* xc = xb + (size_t)c*HW;
        float val = w00*xc[i00] + w01*xc[i01] + w10*xc[i10] + w11*xc[i11];
        vb[(size_t)c*9*HW] = val;
    }
}

// ---------------- launch ----------------
extern "C" void kernel_launch(void* const* d_in, const int* in_sizes, int n_in,
                              void* d_out, int out_size)
{
    const float* R1    = (const float*)d_in[0];
    const float* Q0    = (const float*)d_in[1];
    const float* w1    = (const float*)d_in[2];
    const float* b1    = (const float*)d_in[3];
    const float* w2    = (const float*)d_in[4];
    const float* b2    = (const float*)d_in[5];
    const float* w_om  = (const float*)d_in[6];
    const float* b_om  = (const float*)d_in[7];
    const float* w_dcn = (const float*)d_in[8];
    const float* b_dcn = (const float*)d_in[9];
    const float* w_rq  = (const float*)d_in[10];
    const float* b_rq  = (const float*)d_in[11];
    float* out = (float*)d_out;

    float *t1, *t2, *tom, *tv, *tfea, *pk1, *pk2, *pkom, *pkdc, *pkrq;
    cudaGetSymbolAddress((void**)&t1,   g_t1);
    cudaGetSymbolAddress((void**)&t2,   g_t2);
    cudaGetSymbolAddress((void**)&tom,  g_tom);
    cudaGetSymbolAddress((void**)&tv,   g_tv);
    cudaGetSymbolAddress((void**)&tfea, g_tfea);
    cudaGetSymbolAddress((void**)&pk1,  g_pk1);
    cudaGetSymbolAddress((void**)&pk2,  g_pk2);
    cudaGetSymbolAddress((void**)&pkom, g_pkom);
    cudaGetSymbolAddress((void**)&pkdc, g_pkdc);
    cudaGetSymbolAddress((void**)&pkrq, g_pkrq);

    // ---- pack weights into fragment order (hi/lo tf32) ----
    pack_w<<<(36864 + 255)/256, 256>>>(w1,    pk1,  128, 128,  9, 2);
    pack_w<<<(36864 + 255)/256, 256>>>(w2,    pk2,  128, 128,  9, 2);
    pack_w<<<(73728 + 255)/256, 256>>>(w_om,  pkom, 216, 128,  9, 4);
    pack_w<<<(36864 + 255)/256, 256>>>(w_dcn, pkdc, 128, 1152, 1, 2);
    pack_w<<<(73728 + 255)/256, 256>>>(w_rq,  pkrq, 128, 256,  9, 2);

    dim3 blk(256);
    // spatial grid: x = 96/32 = 3, y = 96/4 = 24, z = BSZ * OCT

    convmma_k<128,128,3,1,true ><<<dim3(3,24,BSZ*2), blk>>>(R1, Q0, pk1, b1, t1);
    convmma_k<128,128,3,0,true ><<<dim3(3,24,BSZ*2), blk>>>(t1, nullptr, pk2, b2, t2);
    convmma_k<128,216,3,0,false><<<dim3(3,24,BSZ*4), blk>>>(t2, nullptr, pkom, b_om, tom);
    dcn_sample_k<<<(BSZ*G*K*HW + 255)/256, 256>>>(R1, tom, tv);
    convmma_k<1152,128,1,0,true><<<dim3(3,24,BSZ*2), blk>>>(tv, nullptr, pkdc, b_dcn, tfea);
    convmma_k<256,128,3,2,true ><<<dim3(3,24,BSZ*2), blk>>>(tfea, Q0, pkrq, b_rq, out);
}